// round 6
// baseline (speedup 1.0000x reference)
#include <cuda_runtime.h>

// Multi-threshold spiking neuron scan (T=4 timesteps, K=8 thresholds).
// x: [T*B, C, H, W] fp32; thresh: scalar fp32.
// Per spatial element, sequentially over T:
//   mem += x_t
//   spike = largest thre in {thresh/2^k, k=0..7} with mem >= 0.75*thre, else 0
//   mem -= spike; out_t = spike
// Independent per element -> one streaming pass; mem lives in registers.
// HBM-bound: 256 MiB total traffic; target ~6.3 TB/s LTS ceiling.

#define T_STEPS 4
#define K_THRESH 8

__device__ __forceinline__ float fire_one(float& mem, float thresh) {
    // k = 7..0 (ascending thresholds): overwrite on each crossing; since
    // crossings are monotone in k, final value = largest crossed threshold,
    // matching the reference's pos_true (first/largest threshold only).
    float spike = 0.0f;
    float th = thresh * 0.0078125f;        // thresh / 128 (exact pow-2)
    #pragma unroll
    for (int k = 0; k < K_THRESH; ++k) {
        spike = (mem >= 0.75f * th) ? th : spike;   // 0.75*th exact
        th = th + th;                               // exact doubling
    }
    mem -= spike;
    return spike;
}

__global__ void __launch_bounds__(256)
snn_scan_kernel(const float4* __restrict__ x,
                const float* __restrict__ thresh_ptr,
                float4* __restrict__ out,
                int n4_per_t)   // float4 count per timestep
{
    const int i = blockIdx.x * blockDim.x + threadIdx.x;
    if (i >= n4_per_t) return;

    const float thresh = __ldg(thresh_ptr);

    // Front-batch all T loads: 4 independent LDG.128 in flight (MLP=4).
    float4 xv[T_STEPS];
    #pragma unroll
    for (int t = 0; t < T_STEPS; ++t)
        xv[t] = __ldg(&x[(size_t)t * n4_per_t + i]);

    float4 mem = make_float4(0.f, 0.f, 0.f, 0.f);

    #pragma unroll
    for (int t = 0; t < T_STEPS; ++t) {
        mem.x += xv[t].x;
        mem.y += xv[t].y;
        mem.z += xv[t].z;
        mem.w += xv[t].w;

        float4 sp;
        sp.x = fire_one(mem.x, thresh);
        sp.y = fire_one(mem.y, thresh);
        sp.z = fire_one(mem.z, thresh);
        sp.w = fire_one(mem.w, thresh);

        out[(size_t)t * n4_per_t + i] = sp;   // fire-and-forget STG.128
    }
}

extern "C" void kernel_launch(void* const* d_in, const int* in_sizes, int n_in,
                              void* d_out, int out_size) {
    const float4* x = (const float4*)d_in[0];
    const float* thresh = (const float*)d_in[1];
    float4* out = (float4*)d_out;

    const int n_total = in_sizes[0];          // T*B*C*H*W = 33,554,432
    const int n_per_t = n_total / T_STEPS;    // 8,388,608
    const int n4 = n_per_t / 4;               // 2,097,152 float4 per timestep

    const int threads = 256;
    const int blocks = (n4 + threads - 1) / threads;
    snn_scan_kernel<<<blocks, threads>>>(x, thresh, out, n4);
}

// round 8
// speedup vs baseline: 1.0007x; 1.0007x over previous
#include <cuda_runtime.h>

// Multi-threshold spiking neuron scan (T=4 timesteps, K=8 thresholds).
// x: [T*B, C, H, W] fp32; thresh: scalar fp32 (positive).
// Per spatial element, sequentially over T:
//   mem += x_t
//   spike = largest thre in {thresh/2^k, k=0..7} with mem >= 0.75*thre, else 0
//   mem -= spike; out_t = spike
//
// Bit-trick firing (exact, no fp rounding differences vs reference):
// For positive normalized floats, ordering of values == ordering of raw bits,
// and bits(v * 2^-k) = bits(v) - (k << 23). With T_k = bits(0.75*thresh) - (k<<23):
//   mem >= 0.75*thresh*2^-k  <=>  mem_bits >= T_k   (integer compare)
// Smallest such k (largest threshold) = ceil((T_0 - mem_bits) / 2^23), clamped
// to [0,7]; fires iff mem_bits >= T_7. spike = int_as_float(thresh_bits - (k<<23)).
// All thresholds are exact pow-2 scalings -> bitwise identical to the reference.

#define T_STEPS 4

__device__ __forceinline__ float fire_one(float& mem, int t0_plus, int t7, int thresh_bits) {
    const int mb  = __float_as_int(mem);
    // clamp into [T7, T0-ish] so the ceil-div lands in [0,7] with no overflow
    int mbc = mb;
    mbc = (mbc < t7) ? t7 : mbc;                     // IMNMX
    const int t0 = t0_plus - 0x7FFFFF;
    mbc = (mbc > t0) ? t0 : mbc;                     // IMNMX
    const int k  = (t0_plus - mbc) >> 23;            // ceil((T0 - mb)/2^23), in [0,7]
    float spike  = __int_as_float(thresh_bits - (k << 23));  // thresh * 2^-k, exact
    spike = (mb >= t7) ? spike : 0.0f;               // no threshold crossed
    mem -= spike;
    return spike;
}

__global__ void __launch_bounds__(256)
snn_scan_kernel(const float4* __restrict__ x,
                const float* __restrict__ thresh_ptr,
                float4* __restrict__ out,
                int n4_per_t)   // float4 count per timestep
{
    const int i = blockIdx.x * blockDim.x + threadIdx.x;
    if (i >= n4_per_t) return;

    const float thresh = __ldg(thresh_ptr);
    const int thresh_bits = __float_as_int(thresh);
    const int t0      = __float_as_int(0.75f * thresh);   // exact (x0.75 of pow2-scaled)
    const int t0_plus = t0 + 0x7FFFFF;
    const int t7      = t0 - (7 << 23);                   // bits(0.75*thresh*2^-7)

    // Front-batch all T loads: 4 independent LDG.128 in flight.
    float4 xv[T_STEPS];
    #pragma unroll
    for (int t = 0; t < T_STEPS; ++t)
        xv[t] = __ldg(&x[(size_t)t * n4_per_t + i]);

    float4 mem = make_float4(0.f, 0.f, 0.f, 0.f);

    #pragma unroll
    for (int t = 0; t < T_STEPS; ++t) {
        mem.x += xv[t].x;
        mem.y += xv[t].y;
        mem.z += xv[t].z;
        mem.w += xv[t].w;

        float4 sp;
        sp.x = fire_one(mem.x, t0_plus, t7, thresh_bits);
        sp.y = fire_one(mem.y, t0_plus, t7, thresh_bits);
        sp.z = fire_one(mem.z, t0_plus, t7, thresh_bits);
        sp.w = fire_one(mem.w, t0_plus, t7, thresh_bits);

        out[(size_t)t * n4_per_t + i] = sp;   // fire-and-forget STG.128
    }
}

extern "C" void kernel_launch(void* const* d_in, const int* in_sizes, int n_in,
                              void* d_out, int out_size) {
    const float4* x = (const float4*)d_in[0];
    const float* thresh = (const float*)d_in[1];
    float4* out = (float4*)d_out;

    const int n_total = in_sizes[0];          // T*B*C*H*W = 33,554,432
    const int n_per_t = n_total / T_STEPS;    // 8,388,608
    const int n4 = n_per_t / 4;               // 2,097,152 float4 per timestep

    const int threads = 256;
    const int blocks = (n4 + threads - 1) / threads;
    snn_scan_kernel<<<blocks, threads>>>(x, thresh, out, n4);
}